// round 4
// baseline (speedup 1.0000x reference)
#include <cuda_runtime.h>
#include <cstdint>

#define B_ 8
#define T_ 1024
#define E_ 1024
#define H_ 16
#define D_ 64
#define M_ (B_*T_)   // 8192 rows

// Scratch (allocation-free rule: __device__ globals)
__device__ float g_Q[B_*H_*T_*D_];
__device__ float g_K[B_*H_*T_*D_];
__device__ float g_V[B_*H_*T_*D_];
__device__ float g_C[M_*E_];

// ---------------------------------------------------------------------------
// Packed f32x2 helpers (PTX fma.rn.f32x2 — SASS FFMA2, 2x fp32 throughput;
// family-wide sm_100+ instruction, no 'a'-suffix target needed)
// ---------------------------------------------------------------------------
typedef unsigned long long u64t;

__device__ __forceinline__ u64t pk2(float lo, float hi) {
    u64t r; asm("mov.b64 %0, {%1, %2};" : "=l"(r) : "f"(lo), "f"(hi)); return r;
}
__device__ __forceinline__ void upk2(u64t v, float& lo, float& hi) {
    asm("mov.b64 {%0, %1}, %2;" : "=f"(lo), "=f"(hi) : "l"(v));
}
__device__ __forceinline__ void fma2(u64t& d, u64t a, u64t b) {
    asm("fma.rn.f32x2 %0, %1, %2, %0;" : "+l"(d) : "l"(a), "l"(b));
}
__device__ __forceinline__ void mul2(u64t& d, u64t a) {
    asm("mul.rn.f32x2 %0, %0, %1;" : "+l"(d) : "l"(a));
}

// ---------------------------------------------------------------------------
// GEMM: Y[m,n] = sum_k X[m,k] * W[n,k] + bias[n]  (FFMA2 inner loop)
// Tile 128x128xK8, 256 threads, 8x8 per-thread register tile (packed 8x4 f32x2).
// BHTD=1: scatter output to (B,H,T,D). BHTD=0: row-major.
// ---------------------------------------------------------------------------
template<int BHTD>
__global__ void __launch_bounds__(256)
gemm_bias(const float* __restrict__ X, const float* __restrict__ W,
          const float* __restrict__ bias, float* __restrict__ Y)
{
    __shared__ float As[8][132];
    __shared__ float Bs[8][132];

    const int tid = threadIdx.x;
    const int tx  = tid & 15;
    const int ty  = tid >> 4;
    const int m0  = blockIdx.y * 128;
    const int n0  = blockIdx.x * 128;

    u64t acc2[8][4];
#pragma unroll
    for (int i = 0; i < 8; ++i)
#pragma unroll
        for (int j = 0; j < 4; ++j) acc2[i][j] = 0ULL;

    const int lRow = tid >> 1;
    const int lCol = (tid & 1) * 4;
    const float* Xp = X + (size_t)(m0 + lRow) * E_ + lCol;
    const float* Wp = W + (size_t)(n0 + lRow) * E_ + lCol;

    for (int k0 = 0; k0 < E_; k0 += 8) {
        float4 av = *(const float4*)(Xp + k0);
        float4 bv = *(const float4*)(Wp + k0);
        As[lCol+0][lRow] = av.x; As[lCol+1][lRow] = av.y;
        As[lCol+2][lRow] = av.z; As[lCol+3][lRow] = av.w;
        Bs[lCol+0][lRow] = bv.x; Bs[lCol+1][lRow] = bv.y;
        Bs[lCol+2][lRow] = bv.z; Bs[lCol+3][lRow] = bv.w;
        __syncthreads();

#pragma unroll
        for (int kk = 0; kk < 8; ++kk) {
            float4 t0 = *(const float4*)&As[kk][ty*8];
            float4 t1 = *(const float4*)&As[kk][ty*8+4];
            const ulonglong2* bp = (const ulonglong2*)&Bs[kk][tx*8];
            ulonglong2 b01 = bp[0];
            ulonglong2 b23 = bp[1];
            u64t b2[4] = { b01.x, b01.y, b23.x, b23.y };
            float a[8] = { t0.x, t0.y, t0.z, t0.w, t1.x, t1.y, t1.z, t1.w };
#pragma unroll
            for (int i = 0; i < 8; ++i) {
                u64t ab = pk2(a[i], a[i]);
#pragma unroll
                for (int j = 0; j < 4; ++j) fma2(acc2[i][j], ab, b2[j]);
            }
        }
        __syncthreads();
    }

#pragma unroll
    for (int i = 0; i < 8; ++i) {
        const int m = m0 + ty*8 + i;
        float o[8];
#pragma unroll
        for (int j = 0; j < 4; ++j) upk2(acc2[i][j], o[2*j], o[2*j+1]);
#pragma unroll
        for (int j = 0; j < 8; j += 4) {
            const int n = n0 + tx*8 + j;
            float4 v;
            v.x = o[j+0] + bias[n+0];
            v.y = o[j+1] + bias[n+1];
            v.z = o[j+2] + bias[n+2];
            v.w = o[j+3] + bias[n+3];
            if (BHTD) {
                const int b = m >> 10, t = m & (T_-1);
                const int h = n >> 6,  d = n & 63;
                *(float4*)&Y[((((size_t)b*H_ + h)*T_) + t)*D_ + d] = v;
            } else {
                *(float4*)&Y[(size_t)m*E_ + n] = v;
            }
        }
    }
}

// ---------------------------------------------------------------------------
// Flash-style attention, fp32 with FFMA2 inner loops.
// One CTA per (bh, 64-row q tile), Bc=64, 16x16 threads.
// Qs/Ks/Ps stride 66 (even -> 8B-aligned d-pairs; 66%32=2 -> conflict-free
// Ks row reads). Vs stride 68 (16B-aligned float4 rows).
// QK^T: packed over d-parity, horizontal add at tile end.
// PV:   packed over output-column pairs.
// ---------------------------------------------------------------------------
__global__ void __launch_bounds__(256)
attn_kernel(const float* __restrict__ Q, const float* __restrict__ K,
            const float* __restrict__ V, float* __restrict__ ctx)
{
    extern __shared__ float smf[];
    float* Qs = smf;                // [64][66]
    float* Ks = smf + 64*66;        // [64][66]
    float* Ps = smf + 2*64*66;      // [64][66]
    float* Vs = smf + 3*64*66;      // [64][68], byte offset 50688 (16B aligned)

    const int tid = threadIdx.x;
    const int tx  = tid & 15;
    const int ty  = tid >> 4;
    const int bh  = blockIdx.y;
    const int q0  = blockIdx.x * 64;

    const float* Qg = Q + ((size_t)bh*T_ + q0) * D_;
    const float* Kg = K + (size_t)bh*T_*D_;
    const float* Vg = V + (size_t)bh*T_*D_;

    // Load Q tile, pre-scaled by 1/sqrt(D)=0.125
#pragma unroll
    for (int i = 0; i < 4; ++i) {
        const int lin = tid + i*256;
        const int r   = lin >> 4;
        const int c4  = (lin & 15) * 4;
        float4 v = *(const float4*)(Qg + r*D_ + c4);
        Qs[r*66 + c4+0] = v.x * 0.125f;
        Qs[r*66 + c4+1] = v.y * 0.125f;
        Qs[r*66 + c4+2] = v.z * 0.125f;
        Qs[r*66 + c4+3] = v.w * 0.125f;
    }

    float m_i[4], l_i[4];
    u64t acc2[4][2];
#pragma unroll
    for (int i = 0; i < 4; ++i) {
        m_i[i] = -1e30f; l_i[i] = 0.f;
        acc2[i][0] = 0ULL; acc2[i][1] = 0ULL;
    }

    for (int kt = 0; kt < T_; kt += 64) {
        __syncthreads();
#pragma unroll
        for (int i = 0; i < 4; ++i) {
            const int lin = tid + i*256;
            const int r   = lin >> 4;
            const int c4  = (lin & 15) * 4;
            float4 kv = *(const float4*)(Kg + (size_t)(kt + r)*D_ + c4);
            Ks[r*66 + c4+0] = kv.x; Ks[r*66 + c4+1] = kv.y;
            Ks[r*66 + c4+2] = kv.z; Ks[r*66 + c4+3] = kv.w;
            float4 vv = *(const float4*)(Vg + (size_t)(kt + r)*D_ + c4);
            *(float4*)&Vs[r*68 + c4] = vv;
        }
        __syncthreads();

        // S = (Q/8) K^T, packed over d-parity
        u64t s2[4][4];
#pragma unroll
        for (int i = 0; i < 4; ++i)
#pragma unroll
            for (int j = 0; j < 4; ++j) s2[i][j] = 0ULL;

#pragma unroll 8
        for (int d = 0; d < 64; d += 2) {
            u64t q2[4], k2[4];
#pragma unroll
            for (int i = 0; i < 4; ++i)
                q2[i] = *(const u64t*)&Qs[(ty*4+i)*66 + d];
            k2[0] = *(const u64t*)&Ks[(tx +  0)*66 + d];
            k2[1] = *(const u64t*)&Ks[(tx + 16)*66 + d];
            k2[2] = *(const u64t*)&Ks[(tx + 32)*66 + d];
            k2[3] = *(const u64t*)&Ks[(tx + 48)*66 + d];
#pragma unroll
            for (int i = 0; i < 4; ++i)
#pragma unroll
                for (int j = 0; j < 4; ++j)
                    fma2(s2[i][j], q2[i], k2[j]);
        }

        // horizontal add of even/odd partials
        float s[4][4];
#pragma unroll
        for (int i = 0; i < 4; ++i)
#pragma unroll
            for (int j = 0; j < 4; ++j) {
                float lo, hi; upk2(s2[i][j], lo, hi);
                s[i][j] = lo + hi;
            }

        // Online softmax per row (row owned by 16 tx-lanes)
#pragma unroll
        for (int i = 0; i < 4; ++i) {
            float mx = fmaxf(fmaxf(s[i][0], s[i][1]), fmaxf(s[i][2], s[i][3]));
            mx = fmaxf(mx, __shfl_xor_sync(0xffffffffu, mx, 8));
            mx = fmaxf(mx, __shfl_xor_sync(0xffffffffu, mx, 4));
            mx = fmaxf(mx, __shfl_xor_sync(0xffffffffu, mx, 2));
            mx = fmaxf(mx, __shfl_xor_sync(0xffffffffu, mx, 1));
            const float mnew  = fmaxf(m_i[i], mx);
            const float alpha = __expf(m_i[i] - mnew);
            m_i[i] = mnew;
            float rs = 0.f;
#pragma unroll
            for (int j = 0; j < 4; ++j) { s[i][j] = __expf(s[i][j] - mnew); rs += s[i][j]; }
            rs += __shfl_xor_sync(0xffffffffu, rs, 8);
            rs += __shfl_xor_sync(0xffffffffu, rs, 4);
            rs += __shfl_xor_sync(0xffffffffu, rs, 2);
            rs += __shfl_xor_sync(0xffffffffu, rs, 1);
            l_i[i] = l_i[i]*alpha + rs;
            u64t al = pk2(alpha, alpha);
            mul2(acc2[i][0], al);
            mul2(acc2[i][1], al);
        }

        // Stage P to smem
#pragma unroll
        for (int i = 0; i < 4; ++i)
#pragma unroll
            for (int j = 0; j < 4; ++j)
                Ps[(ty*4+i)*66 + tx + 16*j] = s[i][j];
        __syncthreads();

        // O += P @ V, packed over output-column pairs, c unrolled by 2
#pragma unroll 4
        for (int c = 0; c < 64; c += 2) {
            u64t p01[4];
#pragma unroll
            for (int i = 0; i < 4; ++i)
                p01[i] = *(const u64t*)&Ps[(ty*4+i)*66 + c];
            ulonglong2 v0 = *(const ulonglong2*)&Vs[(c+0)*68 + tx*4];
            ulonglong2 v1 = *(const ulonglong2*)&Vs[(c+1)*68 + tx*4];
#pragma unroll
            for (int i = 0; i < 4; ++i) {
                float p0, p1; upk2(p01[i], p0, p1);
                u64t pb0 = pk2(p0, p0);
                u64t pb1 = pk2(p1, p1);
                fma2(acc2[i][0], pb0, v0.x);
                fma2(acc2[i][1], pb0, v0.y);
                fma2(acc2[i][0], pb1, v1.x);
                fma2(acc2[i][1], pb1, v1.y);
            }
        }
    }

    // Write ctx in (B, T, E) layout: ctx[b, t, h*64 + d]
    const int b = bh >> 4;
    const int h = bh & 15;
#pragma unroll
    for (int i = 0; i < 4; ++i) {
        const float inv = 1.f / l_i[i];
        const int t = q0 + ty*4 + i;
        float o0, o1, o2, o3;
        upk2(acc2[i][0], o0, o1);
        upk2(acc2[i][1], o2, o3);
        float4 o;
        o.x = o0*inv; o.y = o1*inv; o.z = o2*inv; o.w = o3*inv;
        *(float4*)&ctx[((size_t)b*T_ + t)*E_ + h*64 + tx*4] = o;
    }
}

// ---------------------------------------------------------------------------
extern "C" void kernel_launch(void* const* d_in, const int* in_sizes, int n_in,
                              void* d_out, int out_size)
{
    const float* query = (const float*)d_in[0];
    const float* key   = (const float*)d_in[1];
    const float* value = (const float*)d_in[2];
    const float* Wq = (const float*)d_in[3];  const float* bq = (const float*)d_in[4];
    const float* Wk = (const float*)d_in[5];  const float* bk = (const float*)d_in[6];
    const float* Wv = (const float*)d_in[7];  const float* bv = (const float*)d_in[8];
    const float* Wo = (const float*)d_in[9];  const float* bo = (const float*)d_in[10];
    float* out = (float*)d_out;

    float *Qb, *Kb, *Vb, *Cb;
    cudaGetSymbolAddress((void**)&Qb, g_Q);
    cudaGetSymbolAddress((void**)&Kb, g_K);
    cudaGetSymbolAddress((void**)&Vb, g_V);
    cudaGetSymbolAddress((void**)&Cb, g_C);

    const dim3 gGrid(E_/128, M_/128);   // (8, 64)

    gemm_bias<1><<<gGrid, 256>>>(query, Wq, bq, Qb);
    gemm_bias<1><<<gGrid, 256>>>(key,   Wk, bk, Kb);
    gemm_bias<1><<<gGrid, 256>>>(value, Wv, bv, Vb);

    const int attn_smem = (3*64*66 + 64*68) * (int)sizeof(float);   // 68096 B
    cudaFuncSetAttribute(attn_kernel, cudaFuncAttributeMaxDynamicSharedMemorySize, attn_smem);
    attn_kernel<<<dim3(T_/64, B_*H_), 256, attn_smem>>>(Qb, Kb, Vb, Cb);

    gemm_bias<0><<<gGrid, 256>>>(Cb, Wo, bo, out);
}

// round 8
// speedup vs baseline: 1.0926x; 1.0926x over previous
#include <cuda_runtime.h>
#include <cstdint>

#define B_ 8
#define T_ 1024
#define E_ 1024
#define H_ 16
#define D_ 64
#define M_ (B_*T_)   // 8192 rows

// Scratch (allocation-free rule: __device__ globals)
__device__ float g_Q[B_*H_*T_*D_];
__device__ float g_K[B_*H_*T_*D_];
__device__ float g_V[B_*H_*T_*D_];
__device__ float g_C[M_*E_];

// ---------------------------------------------------------------------------
// Packed f32x2 helpers (PTX fma.rn.f32x2 — SASS FFMA2; family-wide sm_100+)
// ---------------------------------------------------------------------------
typedef unsigned long long u64t;

__device__ __forceinline__ u64t pk2(float lo, float hi) {
    u64t r; asm("mov.b64 %0, {%1, %2};" : "=l"(r) : "f"(lo), "f"(hi)); return r;
}
__device__ __forceinline__ void upk2(u64t v, float& lo, float& hi) {
    asm("mov.b64 {%0, %1}, %2;" : "=f"(lo), "=f"(hi) : "l"(v));
}
__device__ __forceinline__ void fma2(u64t& d, u64t a, u64t b) {
    asm("fma.rn.f32x2 %0, %1, %2, %0;" : "+l"(d) : "l"(a), "l"(b));
}
__device__ __forceinline__ void mul2(u64t& d, u64t a) {
    asm("mul.rn.f32x2 %0, %0, %1;" : "+l"(d) : "l"(a));
}

// ---------------------------------------------------------------------------
// GEMM body: Y[m,n] = sum_k X[m,k]*W[n,k] + bias[n]
// CTA tile 128x128, 256 threads, 8x8 per-thread (FFMA2-packed 8x4).
// K-slab 16, double-buffered smem, register prefetch of slab s+1 overlapping
// compute of slab s; ONE __syncthreads per 16 kk.
// BHTD=1: scatter output to (B,H,T,D). BHTD=0: row-major.
// ---------------------------------------------------------------------------
template<int BHTD>
__device__ __forceinline__ void gemm_body(
    const float* __restrict__ X, const float* __restrict__ W,
    const float* __restrict__ bias, float* __restrict__ Y)
{
    __shared__ float As[2][16][132];
    __shared__ float Bs[2][16][132];

    const int tid = threadIdx.x;
    const int tx  = tid & 15;
    const int ty  = tid >> 4;
    const int m0  = blockIdx.y * 128;
    const int n0  = blockIdx.x * 128;

    u64t acc2[8][4];
#pragma unroll
    for (int i = 0; i < 8; ++i)
#pragma unroll
        for (int j = 0; j < 4; ++j) acc2[i][j] = 0ULL;

    // loader mapping: thread -> (row, 8-wide k chunk)
    const int lRow = tid >> 1;
    const int kb   = (tid & 1) * 8;
    const float* Xp = X + (size_t)(m0 + lRow) * E_ + kb;
    const float* Wp = W + (size_t)(n0 + lRow) * E_ + kb;

    // preload slab 0
    {
        float4 x0 = *(const float4*)(Xp), x1 = *(const float4*)(Xp + 4);
        float4 w0 = *(const float4*)(Wp), w1 = *(const float4*)(Wp + 4);
        As[0][kb+0][lRow]=x0.x; As[0][kb+1][lRow]=x0.y; As[0][kb+2][lRow]=x0.z; As[0][kb+3][lRow]=x0.w;
        As[0][kb+4][lRow]=x1.x; As[0][kb+5][lRow]=x1.y; As[0][kb+6][lRow]=x1.z; As[0][kb+7][lRow]=x1.w;
        Bs[0][kb+0][lRow]=w0.x; Bs[0][kb+1][lRow]=w0.y; Bs[0][kb+2][lRow]=w0.z; Bs[0][kb+3][lRow]=w0.w;
        Bs[0][kb+4][lRow]=w1.x; Bs[0][kb+5][lRow]=w1.y; Bs[0][kb+6][lRow]=w1.z; Bs[0][kb+7][lRow]=w1.w;
    }
    __syncthreads();

    for (int s = 0; s < 64; ++s) {
        // prefetch slab s+1 into registers (consumed ~2000 cyc later)
        float4 x0, x1, w0, w1;
        const bool pre = (s < 63);
        if (pre) {
            const float* xp = Xp + (s + 1) * 16;
            const float* wp = Wp + (s + 1) * 16;
            x0 = *(const float4*)xp; x1 = *(const float4*)(xp + 4);
            w0 = *(const float4*)wp; w1 = *(const float4*)(wp + 4);
        }
        const int p = s & 1;
#pragma unroll
        for (int kk = 0; kk < 16; ++kk) {
            float4 t0 = *(const float4*)&As[p][kk][ty*8];
            float4 t1 = *(const float4*)&As[p][kk][ty*8 + 4];
            ulonglong2 b01 = *(const ulonglong2*)&Bs[p][kk][tx*8];
            ulonglong2 b23 = *(const ulonglong2*)&Bs[p][kk][tx*8 + 4];
            u64t b2[4] = { b01.x, b01.y, b23.x, b23.y };
            float a[8] = { t0.x, t0.y, t0.z, t0.w, t1.x, t1.y, t1.z, t1.w };
#pragma unroll
            for (int i = 0; i < 8; ++i) {
                u64t ab = pk2(a[i], a[i]);
#pragma unroll
                for (int j = 0; j < 4; ++j) fma2(acc2[i][j], ab, b2[j]);
            }
        }
        if (pre) {
            const int q = p ^ 1;
            As[q][kb+0][lRow]=x0.x; As[q][kb+1][lRow]=x0.y; As[q][kb+2][lRow]=x0.z; As[q][kb+3][lRow]=x0.w;
            As[q][kb+4][lRow]=x1.x; As[q][kb+5][lRow]=x1.y; As[q][kb+6][lRow]=x1.z; As[q][kb+7][lRow]=x1.w;
            Bs[q][kb+0][lRow]=w0.x; Bs[q][kb+1][lRow]=w0.y; Bs[q][kb+2][lRow]=w0.z; Bs[q][kb+3][lRow]=w0.w;
            Bs[q][kb+4][lRow]=w1.x; Bs[q][kb+5][lRow]=w1.y; Bs[q][kb+6][lRow]=w1.z; Bs[q][kb+7][lRow]=w1.w;
        }
        __syncthreads();
    }

    // epilogue
#pragma unroll
    for (int i = 0; i < 8; ++i) {
        const int m = m0 + ty*8 + i;
        float o[8];
#pragma unroll
        for (int j = 0; j < 4; ++j) upk2(acc2[i][j], o[2*j], o[2*j+1]);
#pragma unroll
        for (int j = 0; j < 8; j += 4) {
            const int n = n0 + tx*8 + j;
            float4 v;
            v.x = o[j+0] + bias[n+0];
            v.y = o[j+1] + bias[n+1];
            v.z = o[j+2] + bias[n+2];
            v.w = o[j+3] + bias[n+3];
            if (BHTD) {
                const int b = m >> 10, t = m & (T_-1);
                const int h = n >> 6,  d = n & 63;
                *(float4*)&Y[((((size_t)b*H_ + h)*T_) + t)*D_ + d] = v;
            } else {
                *(float4*)&Y[(size_t)m*E_ + n] = v;
            }
        }
    }
}

// Fused Q/K/V projection: gridDim.z selects (X, W, b, Y)
__global__ void __launch_bounds__(256, 2)
gemm_qkv(const float* __restrict__ q, const float* __restrict__ k,
         const float* __restrict__ v,
         const float* __restrict__ Wq, const float* __restrict__ Wk,
         const float* __restrict__ Wv,
         const float* __restrict__ bq, const float* __restrict__ bk,
         const float* __restrict__ bv,
         float* __restrict__ Qb, float* __restrict__ Kb, float* __restrict__ Vb)
{
    const int z = blockIdx.z;
    const float* X    = (z == 0) ? q  : (z == 1) ? k  : v;
    const float* W    = (z == 0) ? Wq : (z == 1) ? Wk : Wv;
    const float* bias = (z == 0) ? bq : (z == 1) ? bk : bv;
    float*       Y    = (z == 0) ? Qb : (z == 1) ? Kb : Vb;
    gemm_body<1>(X, W, bias, Y);
}

__global__ void __launch_bounds__(256, 2)
gemm_o(const float* __restrict__ X, const float* __restrict__ W,
       const float* __restrict__ bias, float* __restrict__ Y)
{
    gemm_body<0>(X, W, bias, Y);
}

// ---------------------------------------------------------------------------
// Flash-style attention, fp32 + FFMA2, with register prefetch of next K/V tile.
// One CTA per (bh, 64-row q tile), Bc=64, 16x16 threads.
// Qs/Ks/Ps stride 66; Vs stride 68.
// ---------------------------------------------------------------------------
__global__ void __launch_bounds__(256, 2)
attn_kernel(const float* __restrict__ Q, const float* __restrict__ K,
            const float* __restrict__ V, float* __restrict__ ctx)
{
    extern __shared__ float smf[];
    float* Qs = smf;                // [64][66]
    float* Ks = smf + 64*66;        // [64][66]
    float* Ps = smf + 2*64*66;      // [64][66]
    float* Vs = smf + 3*64*66;      // [64][68]

    const int tid = threadIdx.x;
    const int tx  = tid & 15;
    const int ty  = tid >> 4;
    const int bh  = blockIdx.y;
    const int q0  = blockIdx.x * 64;

    const float* Qg = Q + ((size_t)bh*T_ + q0) * D_;
    const float* Kg = K + (size_t)bh*T_*D_;
    const float* Vg = V + (size_t)bh*T_*D_;

    // Load Q tile, pre-scaled by 1/sqrt(D)=0.125
#pragma unroll
    for (int i = 0; i < 4; ++i) {
        const int lin = tid + i*256;
        const int r   = lin >> 4;
        const int c4  = (lin & 15) * 4;
        float4 v = *(const float4*)(Qg + r*D_ + c4);
        Qs[r*66 + c4+0] = v.x * 0.125f;
        Qs[r*66 + c4+1] = v.y * 0.125f;
        Qs[r*66 + c4+2] = v.z * 0.125f;
        Qs[r*66 + c4+3] = v.w * 0.125f;
    }

    // prefetch K/V tile 0 into registers
    float4 kr[4], vr[4];
#pragma unroll
    for (int i = 0; i < 4; ++i) {
        const int lin = tid + i*256;
        const int r   = lin >> 4;
        const int c4  = (lin & 15) * 4;
        kr[i] = *(const float4*)(Kg + (size_t)r*D_ + c4);
        vr[i] = *(const float4*)(Vg + (size_t)r*D_ + c4);
    }

    float m_i[4], l_i[4];
    u64t acc2[4][2];
#pragma unroll
    for (int i = 0; i < 4; ++i) {
        m_i[i] = -1e30f; l_i[i] = 0.f;
        acc2[i][0] = 0ULL; acc2[i][1] = 0ULL;
    }

    for (int t = 0; t < 16; ++t) {
        __syncthreads();   // previous tile's Ks/Vs readers done
        // commit prefetched K/V to smem
#pragma unroll
        for (int i = 0; i < 4; ++i) {
            const int lin = tid + i*256;
            const int r   = lin >> 4;
            const int c4  = (lin & 15) * 4;
            Ks[r*66 + c4+0] = kr[i].x; Ks[r*66 + c4+1] = kr[i].y;
            Ks[r*66 + c4+2] = kr[i].z; Ks[r*66 + c4+3] = kr[i].w;
            *(float4*)&Vs[r*68 + c4] = vr[i];
        }
        __syncthreads();

        // prefetch next tile (overlaps all compute below)
        if (t < 15) {
            const int kt = (t + 1) * 64;
#pragma unroll
            for (int i = 0; i < 4; ++i) {
                const int lin = tid + i*256;
                const int r   = lin >> 4;
                const int c4  = (lin & 15) * 4;
                kr[i] = *(const float4*)(Kg + (size_t)(kt + r)*D_ + c4);
                vr[i] = *(const float4*)(Vg + (size_t)(kt + r)*D_ + c4);
            }
        }

        // S = (Q/8) K^T, packed over d-parity
        u64t s2[4][4];
#pragma unroll
        for (int i = 0; i < 4; ++i)
#pragma unroll
            for (int j = 0; j < 4; ++j) s2[i][j] = 0ULL;

#pragma unroll 8
        for (int d = 0; d < 64; d += 2) {
            u64t q2[4], k2[4];
#pragma unroll
            for (int i = 0; i < 4; ++i)
                q2[i] = *(const u64t*)&Qs[(ty*4+i)*66 + d];
            k2[0] = *(const u64t*)&Ks[(tx +  0)*66 + d];
            k2[1] = *(const u64t*)&Ks[(tx + 16)*66 + d];
            k2[2] = *(const u64t*)&Ks[(tx + 32)*66 + d];
            k2[3] = *(const u64t*)&Ks[(tx + 48)*66 + d];
#pragma unroll
            for (int i = 0; i < 4; ++i)
#pragma unroll
                for (int j = 0; j < 4; ++j)
                    fma2(s2[i][j], q2[i], k2[j]);
        }

        float s[4][4];
#pragma unroll
        for (int i = 0; i < 4; ++i)
#pragma unroll
            for (int j = 0; j < 4; ++j) {
                float lo, hi; upk2(s2[i][j], lo, hi);
                s[i][j] = lo + hi;
            }

        // Online softmax per row
#pragma unroll
        for (int i = 0; i < 4; ++i) {
            float mx = fmaxf(fmaxf(s[i][0], s[i][1]), fmaxf(s[i][2], s[i][3]));
            mx = fmaxf(mx, __shfl_xor_sync(0xffffffffu, mx, 8));
            mx = fmaxf(mx, __shfl_xor_sync(0xffffffffu, mx, 4));
            mx = fmaxf(mx, __shfl_xor_sync(0xffffffffu, mx, 2));
            mx = fmaxf(mx, __shfl_xor_sync(0xffffffffu, mx, 1));
            const float mnew  = fmaxf(m_i[i], mx);
            const float alpha = __expf(m_i[i] - mnew);
            m_i[i] = mnew;
            float rs = 0.f;
#pragma unroll
            for (int j = 0; j < 4; ++j) { s[i][j] = __expf(s[i][j] - mnew); rs += s[i][j]; }
            rs += __shfl_xor_sync(0xffffffffu, rs, 8);
            rs += __shfl_xor_sync(0xffffffffu, rs, 4);
            rs += __shfl_xor_sync(0xffffffffu, rs, 2);
            rs += __shfl_xor_sync(0xffffffffu, rs, 1);
            l_i[i] = l_i[i]*alpha + rs;
            u64t al = pk2(alpha, alpha);
            mul2(acc2[i][0], al);
            mul2(acc2[i][1], al);
        }

        // Stage P to smem
#pragma unroll
        for (int i = 0; i < 4; ++i)
#pragma unroll
            for (int j = 0; j < 4; ++j)
                Ps[(ty*4+i)*66 + tx + 16*j] = s[i][j];
        __syncthreads();

        // O += P @ V, packed over output-column pairs
#pragma unroll 4
        for (int c = 0; c < 64; c += 2) {
            u64t p01[4];
#pragma unroll
            for (int i = 0; i < 4; ++i)
                p01[i] = *(const u64t*)&Ps[(ty*4+i)*66 + c];
            ulonglong2 v0 = *(const ulonglong2*)&Vs[(c+0)*68 + tx*4];
            ulonglong2 v1 = *(const ulonglong2*)&Vs[(c+1)*68 + tx*4];
#pragma unroll
            for (int i = 0; i < 4; ++i) {
                float p0, p1; upk2(p01[i], p0, p1);
                u64t pb0 = pk2(p0, p0);
                u64t pb1 = pk2(p1, p1);
                fma2(acc2[i][0], pb0, v0.x);
                fma2(acc2[i][1], pb0, v0.y);
                fma2(acc2[i][0], pb1, v1.x);
                fma2(acc2[i][1], pb1, v1.y);
            }
        }
    }

    // Write ctx in (B, T, E) layout: ctx[b, t, h*64 + d]
    const int b = bh >> 4;
    const int h = bh & 15;
#pragma unroll
    for (int i = 0; i < 4; ++i) {
        const float inv = 1.f / l_i[i];
        const int t = q0 + ty*4 + i;
        float o0, o1, o2, o3;
        upk2(acc2[i][0], o0, o1);
        upk2(acc2[i][1], o2, o3);
        float4 o;
        o.x = o0*inv; o.y = o1*inv; o.z = o2*inv; o.w = o3*inv;
        *(float4*)&ctx[((size_t)b*T_ + t)*E_ + h*64 + tx*4] = o;
    }
}

// ---------------------------------------------------------------------------
extern "C" void kernel_launch(void* const* d_in, const int* in_sizes, int n_in,
                              void* d_out, int out_size)
{
    const float* query = (const float*)d_in[0];
    const float* key   = (const float*)d_in[1];
    const float* value = (const float*)d_in[2];
    const float* Wq = (const float*)d_in[3];  const float* bq = (const float*)d_in[4];
    const float* Wk = (const float*)d_in[5];  const float* bk = (const float*)d_in[6];
    const float* Wv = (const float*)d_in[7];  const float* bv = (const float*)d_in[8];
    const float* Wo = (const float*)d_in[9];  const float* bo = (const float*)d_in[10];
    float* out = (float*)d_out;

    float *Qb, *Kb, *Vb, *Cb;
    cudaGetSymbolAddress((void**)&Qb, g_Q);
    cudaGetSymbolAddress((void**)&Kb, g_K);
    cudaGetSymbolAddress((void**)&Vb, g_V);
    cudaGetSymbolAddress((void**)&Cb, g_C);

    // fused Q/K/V projections (z selects matrix)
    gemm_qkv<<<dim3(E_/128, M_/128, 3), 256>>>(query, key, value,
                                               Wq, Wk, Wv, bq, bk, bv,
                                               Qb, Kb, Vb);

    const int attn_smem = (3*64*66 + 64*68) * (int)sizeof(float);   // 68096 B
    cudaFuncSetAttribute(attn_kernel, cudaFuncAttributeMaxDynamicSharedMemorySize, attn_smem);
    attn_kernel<<<dim3(T_/64, B_*H_), 256, attn_smem>>>(Qb, Kb, Vb, Cb);

    gemm_o<<<dim3(E_/128, M_/128), 256>>>(Cb, Wo, bo, out);
}

// round 12
// speedup vs baseline: 1.0951x; 1.0023x over previous
#include <cuda_runtime.h>
#include <cstdint>

#define B_ 8
#define T_ 1024
#define E_ 1024
#define H_ 16
#define D_ 64
#define M_ (B_*T_)   // 8192 rows

// Scratch (allocation-free rule: __device__ globals)
__device__ float g_Q[B_*H_*T_*D_];
__device__ float g_K[B_*H_*T_*D_];
__device__ float g_V[B_*H_*T_*D_];
__device__ float g_C[M_*E_];

// ---------------------------------------------------------------------------
// Packed f32x2 helpers (PTX fma.rn.f32x2 — SASS FFMA2; family-wide sm_100+)
// ---------------------------------------------------------------------------
typedef unsigned long long u64t;

__device__ __forceinline__ u64t pk2(float lo, float hi) {
    u64t r; asm("mov.b64 %0, {%1, %2};" : "=l"(r) : "f"(lo), "f"(hi)); return r;
}
__device__ __forceinline__ void upk2(u64t v, float& lo, float& hi) {
    asm("mov.b64 {%0, %1}, %2;" : "=f"(lo), "=f"(hi) : "l"(v));
}
__device__ __forceinline__ void fma2(u64t& d, u64t a, u64t b) {
    asm("fma.rn.f32x2 %0, %1, %2, %0;" : "+l"(d) : "l"(a), "l"(b));
}
__device__ __forceinline__ void mul2(u64t& d, u64t a) {
    asm("mul.rn.f32x2 %0, %0, %1;" : "+l"(d) : "l"(a));
}

// cp.async (LDGSTS) — sm_80+ family-generic, OK under compute_103
__device__ __forceinline__ uint32_t smem_u32(const void* p) {
    uint32_t a;
    asm("{ .reg .u64 t; cvta.to.shared.u64 t, %1; cvt.u32.u64 %0, t; }" : "=r"(a) : "l"(p));
    return a;
}
__device__ __forceinline__ void cpasync16(uint32_t s, const void* g) {
    asm volatile("cp.async.cg.shared.global [%0], [%1], 16;" :: "r"(s), "l"(g));
}
__device__ __forceinline__ void cpasync8(uint32_t s, const void* g) {
    asm volatile("cp.async.ca.shared.global [%0], [%1], 8;" :: "r"(s), "l"(g));
}
#define CP_COMMIT() asm volatile("cp.async.commit_group;" ::: "memory")
#define CP_WAIT(n)  asm volatile("cp.async.wait_group %0;" :: "n"(n) : "memory")

// ---------------------------------------------------------------------------
// GEMM body: Y[m,n] = sum_k X[m,k]*W[n,k] + bias[n]   (unchanged from R8)
// CTA tile 128x128, 256 threads, 8x8 per-thread (FFMA2-packed 8x4).
// K-slab 16, double-buffered smem, register prefetch of slab s+1.
// ---------------------------------------------------------------------------
template<int BHTD>
__device__ __forceinline__ void gemm_body(
    const float* __restrict__ X, const float* __restrict__ W,
    const float* __restrict__ bias, float* __restrict__ Y)
{
    __shared__ float As[2][16][132];
    __shared__ float Bs[2][16][132];

    const int tid = threadIdx.x;
    const int tx  = tid & 15;
    const int ty  = tid >> 4;
    const int m0  = blockIdx.y * 128;
    const int n0  = blockIdx.x * 128;

    u64t acc2[8][4];
#pragma unroll
    for (int i = 0; i < 8; ++i)
#pragma unroll
        for (int j = 0; j < 4; ++j) acc2[i][j] = 0ULL;

    const int lRow = tid >> 1;
    const int kb   = (tid & 1) * 8;
    const float* Xp = X + (size_t)(m0 + lRow) * E_ + kb;
    const float* Wp = W + (size_t)(n0 + lRow) * E_ + kb;

    {
        float4 x0 = *(const float4*)(Xp), x1 = *(const float4*)(Xp + 4);
        float4 w0 = *(const float4*)(Wp), w1 = *(const float4*)(Wp + 4);
        As[0][kb+0][lRow]=x0.x; As[0][kb+1][lRow]=x0.y; As[0][kb+2][lRow]=x0.z; As[0][kb+3][lRow]=x0.w;
        As[0][kb+4][lRow]=x1.x; As[0][kb+5][lRow]=x1.y; As[0][kb+6][lRow]=x1.z; As[0][kb+7][lRow]=x1.w;
        Bs[0][kb+0][lRow]=w0.x; Bs[0][kb+1][lRow]=w0.y; Bs[0][kb+2][lRow]=w0.z; Bs[0][kb+3][lRow]=w0.w;
        Bs[0][kb+4][lRow]=w1.x; Bs[0][kb+5][lRow]=w1.y; Bs[0][kb+6][lRow]=w1.z; Bs[0][kb+7][lRow]=w1.w;
    }
    __syncthreads();

    for (int s = 0; s < 64; ++s) {
        float4 x0, x1, w0, w1;
        const bool pre = (s < 63);
        if (pre) {
            const float* xp = Xp + (s + 1) * 16;
            const float* wp = Wp + (s + 1) * 16;
            x0 = *(const float4*)xp; x1 = *(const float4*)(xp + 4);
            w0 = *(const float4*)wp; w1 = *(const float4*)(wp + 4);
        }
        const int p = s & 1;
#pragma unroll
        for (int kk = 0; kk < 16; ++kk) {
            float4 t0 = *(const float4*)&As[p][kk][ty*8];
            float4 t1 = *(const float4*)&As[p][kk][ty*8 + 4];
            ulonglong2 b01 = *(const ulonglong2*)&Bs[p][kk][tx*8];
            ulonglong2 b23 = *(const ulonglong2*)&Bs[p][kk][tx*8 + 4];
            u64t b2[4] = { b01.x, b01.y, b23.x, b23.y };
            float a[8] = { t0.x, t0.y, t0.z, t0.w, t1.x, t1.y, t1.z, t1.w };
#pragma unroll
            for (int i = 0; i < 8; ++i) {
                u64t ab = pk2(a[i], a[i]);
#pragma unroll
                for (int j = 0; j < 4; ++j) fma2(acc2[i][j], ab, b2[j]);
            }
        }
        if (pre) {
            const int q = p ^ 1;
            As[q][kb+0][lRow]=x0.x; As[q][kb+1][lRow]=x0.y; As[q][kb+2][lRow]=x0.z; As[q][kb+3][lRow]=x0.w;
            As[q][kb+4][lRow]=x1.x; As[q][kb+5][lRow]=x1.y; As[q][kb+6][lRow]=x1.z; As[q][kb+7][lRow]=x1.w;
            Bs[q][kb+0][lRow]=w0.x; Bs[q][kb+1][lRow]=w0.y; Bs[q][kb+2][lRow]=w0.z; Bs[q][kb+3][lRow]=w0.w;
            Bs[q][kb+4][lRow]=w1.x; Bs[q][kb+5][lRow]=w1.y; Bs[q][kb+6][lRow]=w1.z; Bs[q][kb+7][lRow]=w1.w;
        }
        __syncthreads();
    }

#pragma unroll
    for (int i = 0; i < 8; ++i) {
        const int m = m0 + ty*8 + i;
        float o[8];
#pragma unroll
        for (int j = 0; j < 4; ++j) upk2(acc2[i][j], o[2*j], o[2*j+1]);
#pragma unroll
        for (int j = 0; j < 8; j += 4) {
            const int n = n0 + tx*8 + j;
            float4 v;
            v.x = o[j+0] + bias[n+0];
            v.y = o[j+1] + bias[n+1];
            v.z = o[j+2] + bias[n+2];
            v.w = o[j+3] + bias[n+3];
            if (BHTD) {
                const int b = m >> 10, t = m & (T_-1);
                const int h = n >> 6,  d = n & 63;
                *(float4*)&Y[((((size_t)b*H_ + h)*T_) + t)*D_ + d] = v;
            } else {
                *(float4*)&Y[(size_t)m*E_ + n] = v;
            }
        }
    }
}

__global__ void __launch_bounds__(256, 2)
gemm_qkv(const float* __restrict__ q, const float* __restrict__ k,
         const float* __restrict__ v,
         const float* __restrict__ Wq, const float* __restrict__ Wk,
         const float* __restrict__ Wv,
         const float* __restrict__ bq, const float* __restrict__ bk,
         const float* __restrict__ bv,
         float* __restrict__ Qb, float* __restrict__ Kb, float* __restrict__ Vb)
{
    const int z = blockIdx.z;
    const float* X    = (z == 0) ? q  : (z == 1) ? k  : v;
    const float* W    = (z == 0) ? Wq : (z == 1) ? Wk : Wv;
    const float* bias = (z == 0) ? bq : (z == 1) ? bk : bv;
    float*       Y    = (z == 0) ? Qb : (z == 1) ? Kb : Vb;
    gemm_body<1>(X, W, bias, Y);
}

__global__ void __launch_bounds__(256, 2)
gemm_o(const float* __restrict__ X, const float* __restrict__ W,
       const float* __restrict__ bias, float* __restrict__ Y)
{
    gemm_body<0>(X, W, bias, Y);
}

// ---------------------------------------------------------------------------
// Flash-style attention, fp32 + FFMA2.
// K/V tiles loaded via cp.async (no prefetch registers) -> 3 CTAs/SM.
// K tile: 8B cp.async (stride-66 rows are only 8B-aligned). V tile: 16B.
// K committed first: wait_group 1 before QK^T; wait_group 0 folded into the
// P-staging barrier (V landed).
// Qs/Ks/Ps stride 66; Vs stride 68.
// ---------------------------------------------------------------------------
__global__ void __launch_bounds__(256, 3)
attn_kernel(const float* __restrict__ Q, const float* __restrict__ K,
            const float* __restrict__ V, float* __restrict__ ctx)
{
    extern __shared__ float smf[];
    float* Qs = smf;                // [64][66]
    float* Ks = smf + 64*66;        // [64][66]
    float* Ps = smf + 2*64*66;      // [64][66]
    float* Vs = smf + 3*64*66;      // [64][68]

    const int tid = threadIdx.x;
    const int tx  = tid & 15;
    const int ty  = tid >> 4;
    const int bh  = blockIdx.y;
    const int q0  = blockIdx.x * 64;

    const float* Qg = Q + ((size_t)bh*T_ + q0) * D_;
    const float* Kg = K + (size_t)bh*T_*D_;
    const float* Vg = V + (size_t)bh*T_*D_;

    const uint32_t KsA = smem_u32(Ks);
    const uint32_t VsA = smem_u32(Vs);

    // per-thread copy slots: 4 x (row, 16B chunk)
    int rr[4], cc[4];
#pragma unroll
    for (int i = 0; i < 4; ++i) {
        const int lin = tid + i*256;
        rr[i] = lin >> 4;
        cc[i] = (lin & 15) * 4;
    }

    // Load Q tile, pre-scaled by 1/sqrt(D)=0.125
#pragma unroll
    for (int i = 0; i < 4; ++i) {
        float4 v = *(const float4*)(Qg + rr[i]*D_ + cc[i]);
        float* q = &Qs[rr[i]*66 + cc[i]];
        q[0] = v.x * 0.125f; q[1] = v.y * 0.125f;
        q[2] = v.z * 0.125f; q[3] = v.w * 0.125f;
    }

    float m_i[4], l_i[4];
    u64t acc2[4][2];
#pragma unroll
    for (int i = 0; i < 4; ++i) {
        m_i[i] = -1e30f; l_i[i] = 0.f;
        acc2[i][0] = 0ULL; acc2[i][1] = 0ULL;
    }

    for (int t = 0; t < 16; ++t) {
        __syncthreads();   // previous tile's Ks/Vs readers done (also orders Qs stores at t=0)
        const int kt = t * 64;
        // async-copy K tile: 2x 8B per slot (stride-66 rows are 8B-aligned only)
#pragma unroll
        for (int i = 0; i < 4; ++i) {
            const uint32_t sdst = KsA + (uint32_t)(rr[i]*66 + cc[i])*4u;
            const float*  gsrc = Kg + (size_t)(kt + rr[i])*D_ + cc[i];
            cpasync8(sdst,      gsrc);
            cpasync8(sdst + 8u, gsrc + 2);
        }
        CP_COMMIT();
        // async-copy V tile: 16B (stride-68 rows are 16B-aligned)
#pragma unroll
        for (int i = 0; i < 4; ++i)
            cpasync16(VsA + (uint32_t)(rr[i]*68 + cc[i])*4u,
                      Vg + (size_t)(kt + rr[i])*D_ + cc[i]);
        CP_COMMIT();

        CP_WAIT(1);        // K group complete (V may still be in flight)
        __syncthreads();   // K visible CTA-wide

        // S = (Q/8) K^T, packed over d-parity
        u64t s2[4][4];
#pragma unroll
        for (int i = 0; i < 4; ++i)
#pragma unroll
            for (int j = 0; j < 4; ++j) s2[i][j] = 0ULL;

#pragma unroll 8
        for (int d = 0; d < 64; d += 2) {
            u64t q2[4], k2[4];
#pragma unroll
            for (int i = 0; i < 4; ++i)
                q2[i] = *(const u64t*)&Qs[(ty*4+i)*66 + d];
            k2[0] = *(const u64t*)&Ks[(tx +  0)*66 + d];
            k2[1] = *(const u64t*)&Ks[(tx + 16)*66 + d];
            k2[2] = *(const u64t*)&Ks[(tx + 32)*66 + d];
            k2[3] = *(const u64t*)&Ks[(tx + 48)*66 + d];
#pragma unroll
            for (int i = 0; i < 4; ++i)
#pragma unroll
                for (int j = 0; j < 4; ++j)
                    fma2(s2[i][j], q2[i], k2[j]);
        }

        float s[4][4];
#pragma unroll
        for (int i = 0; i < 4; ++i)
#pragma unroll
            for (int j = 0; j < 4; ++j) {
                float lo, hi; upk2(s2[i][j], lo, hi);
                s[i][j] = lo + hi;
            }

        // Online softmax per row
#pragma unroll
        for (int i = 0; i < 4; ++i) {
            float mx = fmaxf(fmaxf(s[i][0], s[i][1]), fmaxf(s[i][2], s[i][3]));
            mx = fmaxf(mx, __shfl_xor_sync(0xffffffffu, mx, 8));
            mx = fmaxf(mx, __shfl_xor_sync(0xffffffffu, mx, 4));
            mx = fmaxf(mx, __shfl_xor_sync(0xffffffffu, mx, 2));
            mx = fmaxf(mx, __shfl_xor_sync(0xffffffffu, mx, 1));
            const float mnew  = fmaxf(m_i[i], mx);
            const float alpha = __expf(m_i[i] - mnew);
            m_i[i] = mnew;
            float rs = 0.f;
#pragma unroll
            for (int j = 0; j < 4; ++j) { s[i][j] = __expf(s[i][j] - mnew); rs += s[i][j]; }
            rs += __shfl_xor_sync(0xffffffffu, rs, 8);
            rs += __shfl_xor_sync(0xffffffffu, rs, 4);
            rs += __shfl_xor_sync(0xffffffffu, rs, 2);
            rs += __shfl_xor_sync(0xffffffffu, rs, 1);
            l_i[i] = l_i[i]*alpha + rs;
            u64t al = pk2(alpha, alpha);
            mul2(acc2[i][0], al);
            mul2(acc2[i][1], al);
        }

        // Stage P to smem
#pragma unroll
        for (int i = 0; i < 4; ++i)
#pragma unroll
            for (int j = 0; j < 4; ++j)
                Ps[(ty*4+i)*66 + tx + 16*j] = s[i][j];

        CP_WAIT(0);        // V group complete (thread-local)
        __syncthreads();   // Ps + Vs visible CTA-wide

        // O += P @ V, packed over output-column pairs
#pragma unroll 4
        for (int c = 0; c < 64; c += 2) {
            u64t p01[4];
#pragma unroll
            for (int i = 0; i < 4; ++i)
                p01[i] = *(const u64t*)&Ps[(ty*4+i)*66 + c];
            ulonglong2 v0 = *(const ulonglong2*)&Vs[(c+0)*68 + tx*4];
            ulonglong2 v1 = *(const ulonglong2*)&Vs[(c+1)*68 + tx*4];
#pragma unroll
            for (int i = 0; i < 4; ++i) {
                float p0, p1; upk2(p01[i], p0, p1);
                u64t pb0 = pk2(p0, p0);
                u64t pb1 = pk2(p1, p1);
                fma2(acc2[i][0], pb0, v0.x);
                fma2(acc2[i][1], pb0, v0.y);
                fma2(acc2[i][0], pb1, v1.x);
                fma2(acc2[i][1], pb1, v1.y);
            }
        }
    }

    // Write ctx in (B, T, E) layout: ctx[b, t, h*64 + d]
    const int b = bh >> 4;
    const int h = bh & 15;
#pragma unroll
    for (int i = 0; i < 4; ++i) {
        const float inv = 1.f / l_i[i];
        const int t = q0 + ty*4 + i;
        float o0, o1, o2, o3;
        upk2(acc2[i][0], o0, o1);
        upk2(acc2[i][1], o2, o3);
        float4 o;
        o.x = o0*inv; o.y = o1*inv; o.z = o2*inv; o.w = o3*inv;
        *(float4*)&ctx[((size_t)b*T_ + t)*E_ + h*64 + tx*4] = o;
    }
}

// ---------------------------------------------------------------------------
extern "C" void kernel_launch(void* const* d_in, const int* in_sizes, int n_in,
                              void* d_out, int out_size)
{
    const float* query = (const float*)d_in[0];
    const float* key   = (const float*)d_in[1];
    const float* value = (const float*)d_in[2];
    const float* Wq = (const float*)d_in[3];  const float* bq = (const float*)d_in[4];
    const float* Wk = (const float*)d_in[5];  const float* bk = (const float*)d_in[6];
    const float* Wv = (const float*)d_in[7];  const float* bv = (const float*)d_in[8];
    const float* Wo = (const float*)d_in[9];  const float* bo = (const float*)d_in[10];
    float* out = (float*)d_out;

    float *Qb, *Kb, *Vb, *Cb;
    cudaGetSymbolAddress((void**)&Qb, g_Q);
    cudaGetSymbolAddress((void**)&Kb, g_K);
    cudaGetSymbolAddress((void**)&Vb, g_V);
    cudaGetSymbolAddress((void**)&Cb, g_C);

    // fused Q/K/V projections (z selects matrix)
    gemm_qkv<<<dim3(E_/128, M_/128, 3), 256>>>(query, key, value,
                                               Wq, Wk, Wv, bq, bk, bv,
                                               Qb, Kb, Vb);

    const int attn_smem = (3*64*66 + 64*68) * (int)sizeof(float);   // 68096 B
    cudaFuncSetAttribute(attn_kernel, cudaFuncAttributeMaxDynamicSharedMemorySize, attn_smem);
    attn_kernel<<<dim3(T_/64, B_*H_), 256, attn_smem>>>(Qb, Kb, Vb, Cb);

    gemm_o<<<dim3(E_/128, M_/128), 256>>>(Cb, Wo, bo, out);
}